// round 10
// baseline (speedup 1.0000x reference)
#include <cuda_runtime.h>

#define B_ 512
#define S_ 512
#define T_ 128
#define NEGV (-10000.0f)
#define END_ID 1
#define L2E 1.4426950408889634f
#define LN2 0.6931471805599453f
#define NCTA 148

__device__ float g_diff[B_];
__device__ int g_next = 0;
__device__ int g_done = 0;

static __device__ __forceinline__ float ex2(float x) {
    float r; asm("ex2.approx.f32 %0, %1;" : "=f"(r) : "f"(x)); return r;
}
static __device__ __forceinline__ float lg2(float x) {
    float r; asm("lg2.approx.f32 %0, %1;" : "=f"(r) : "f"(x)); return r;
}
static __device__ __forceinline__ unsigned long long pack2(float lo, float hi) {
    unsigned long long r;
    asm("mov.b64 %0, {%1, %2};" : "=l"(r) : "r"(__float_as_uint(lo)), "r"(__float_as_uint(hi)));
    return r;
}
static __device__ __forceinline__ float lo2(unsigned long long v) {
    unsigned int a, b;
    asm("mov.b64 {%0, %1}, %2;" : "=r"(a), "=r"(b) : "l"(v));
    (void)b;
    return __uint_as_float(a);
}
static __device__ __forceinline__ float hi2(unsigned long long v) {
    unsigned int a, b;
    asm("mov.b64 {%0, %1}, %2;" : "=r"(a), "=r"(b) : "l"(v));
    (void)a;
    return __uint_as_float(b);
}
static __device__ __forceinline__ float hsum2(unsigned long long v) {
    unsigned int a, b;
    asm("mov.b64 {%0, %1}, %2;" : "=r"(a), "=r"(b) : "l"(v));
    return __uint_as_float(a) + __uint_as_float(b);
}
#define FMA2(acc, e, a) asm("fma.rn.f32x2 %0, %1, %2, %0;" : "+l"(acc) : "l"(e), "l"(a))
#define ADD2(o, a, b)   asm("add.rn.f32x2 %0, %1, %2;" : "=l"(o) : "l"(a), "l"(b))

static __device__ __forceinline__ float warp_sum(float v) {
#pragma unroll
    for (int o = 16; o; o >>= 1) v += __shfl_xor_sync(0xffffffffu, v, o);
    return v;
}
static __device__ __forceinline__ float warp_max(float v) {
#pragma unroll
    for (int o = 16; o; o >>= 1) v = fmaxf(v, __shfl_xor_sync(0xffffffffu, v, o));
    return v;
}

// 256 threads, TWO independent work-stealing chain slots per CTA, stepped in
// lockstep (amortized barriers). Warp w: half h = w&1 (warp-uniform -> all hot
// LDS broadcasts), tag = (w>>1)*32 + lane. grid=148 -> 1 CTA/SM.
__global__ void __launch_bounds__(256, 1) crf_kernel(
    const float* __restrict__ x,      // [B,S,T]
    const int*   __restrict__ tags,   // [B,S]
    const float* __restrict__ mask,   // [B,S]
    const float* __restrict__ trans,  // [T,T]
    float* __restrict__ out)
{
    const int tid  = threadIdx.x;
    const int lane = tid & 31;
    const int w    = tid >> 5;
    const int grp  = w >> 1;            // 0..3
    const int h    = w & 1;             // warp-uniform half
    const int tag  = grp * 32 + lane;   // 0..127

    __shared__ __align__(16) float saA[2][T_];
    __shared__ __align__(16) float saB[2][T_];
    __shared__ __align__(16) unsigned long long s_part[2 * T_];
    __shared__ unsigned long long s_m[2];
    __shared__ float s_red[8];
    __shared__ int   s_fetch[2];
    __shared__ int   s_last;

#define PBAR() asm volatile("bar.sync %0, 64;" :: "r"(grp + 1) : "memory")

    // ---- E regs: exp(trans[tag, h*64 .. h*64+63]) as 32 packed f32x2 ----
    unsigned long long er[32];
    {
        const float4* tr4 = reinterpret_cast<const float4*>(trans + tag * T_ + h * 64);
#pragma unroll
        for (int j = 0; j < 16; j++) {
            float4 v = __ldg(tr4 + j);
            er[2 * j]     = pack2(ex2(v.x * L2E), ex2(v.y * L2E));
            er[2 * j + 1] = pack2(ex2(v.z * L2E), ex2(v.w * L2E));
        }
    }

    // ---- slot state (len: -1 = needs first fetch, 0 = exhausted, >0 active) ----
    int bA = 0, lenA = -1, tA = 0;
    int bB = 0, lenB = -1, tB = 0;
    float betaA = 0.f, mbA = 0.f, betaB = 0.f, mbB = 0.f;
    const float* xbA = x;
    const float* xbB = x;
    float xrA[4], xrB[4];
#pragma unroll
    for (int d = 0; d < 4; d++) { xrA[d] = 0.f; xrB[d] = 0.f; }

#define EPILOGUE(BB, LL, BETA, XB)                                           \
    {                                                                        \
        float v_ = (h == 0) ? ((BETA) + __ldg(trans + END_ID * T_ + tag) * L2E) \
                            : -3.0e38f;                                      \
        float mx_ = warp_max(v_);                                            \
        __syncthreads();                                                     \
        if (lane == 0) s_red[w] = mx_;                                       \
        __syncthreads();                                                     \
        mx_ = s_red[0];                                                      \
        _Pragma("unroll")                                                    \
        for (int k = 1; k < 8; k++) mx_ = fmaxf(mx_, s_red[k]);              \
        float e2_ = (h == 0) ? ex2(v_ - mx_) : 0.f;                          \
        float se_ = warp_sum(e2_);                                           \
        __syncthreads();                                                     \
        if (lane == 0) s_red[w] = se_;                                       \
        __syncthreads();                                                     \
        float tot_ = 0.f;                                                    \
        _Pragma("unroll")                                                    \
        for (int k = 0; k < 8; k++) tot_ += s_red[k];                        \
        float fwd_ = (mx_ + lg2(tot_)) * LN2;                                \
        const int* tb_ = tags + (BB) * S_;                                   \
        float gs_ = 0.f;                                                     \
        for (int u = tid; u < (LL); u += 256) {                              \
            int tn_ = tb_[u + 1];                                            \
            int tc_ = tb_[u];                                                \
            gs_ += (XB)[(size_t)u * T_ + tn_] + __ldg(trans + tn_ * T_ + tc_); \
        }                                                                    \
        gs_ = warp_sum(gs_);                                                 \
        __syncthreads();                                                     \
        if (lane == 0) s_red[w] = gs_;                                       \
        __syncthreads();                                                     \
        if (tid == 0) {                                                      \
            float gt_ = 0.f;                                                 \
            _Pragma("unroll")                                                \
            for (int k = 0; k < 8; k++) gt_ += s_red[k];                     \
            gt_ += __ldg(trans + END_ID * T_ + tb_[(LL)]);                   \
            g_diff[BB] = fwd_ - gt_;                                         \
        }                                                                    \
        __syncthreads();                                                     \
    }

#define INITSLOT(NB, BV, LENV, TV, BETAV, MBV, XBV, XRV)                     \
    {                                                                        \
        BV = (NB);                                                           \
        XBV = x + (size_t)(NB) * S_ * T_;                                    \
        float lm_ = mask[(NB) * S_ + tid] + mask[(NB) * S_ + tid + 256];     \
        lm_ = warp_sum(lm_);                                                 \
        if (lane == 0) s_red[w] = lm_;                                       \
        __syncthreads();                                                     \
        float lt_ = 0.f;                                                     \
        _Pragma("unroll")                                                    \
        for (int k = 0; k < 8; k++) lt_ += s_red[k];                         \
        LENV = (int)(lt_ + 0.5f);                                            \
        TV = 0;                                                              \
        BETAV = (tag == 0) ? 0.f : NEGV * L2E;                               \
        MBV = 0.f;                                                           \
        _Pragma("unroll")                                                    \
        for (int d_ = 0; d_ < 4; d_++)                                       \
            XRV[d_] = __ldg(XBV + (size_t)min(d_, LENV - 1) * T_ + tag) * L2E; \
        __syncthreads();                                                     \
    }

#define STEP(PP, XA, XB2, ACTA, ACTB)                                        \
    {                                                                        \
        float eA_ = ex2(betaA - mbA);                                        \
        float eB_ = ex2(betaB - mbB);                                        \
        if (h == 0) { saA[PP][tag] = eA_; saB[PP][tag] = eB_; }              \
        if (tid == 0) s_m[PP] = pack2(betaA, betaB);                         \
        __syncthreads();                                                     \
        unsigned long long mp_ = s_m[PP];                                    \
        float mbAn_ = lo2(mp_), mbBn_ = hi2(mp_);                            \
        const ulonglong2* spA_ =                                             \
            reinterpret_cast<const ulonglong2*>(&saA[PP][h * 64]);           \
        const ulonglong2* spB_ =                                             \
            reinterpret_cast<const ulonglong2*>(&saB[PP][h * 64]);           \
        unsigned long long a0_ = 0ull, a1_ = 0ull, a2_ = 0ull, a3_ = 0ull;   \
        unsigned long long c0_ = 0ull, c1_ = 0ull, c2_ = 0ull, c3_ = 0ull;   \
        _Pragma("unroll")                                                    \
        for (int j = 0; j < 16; j += 2) {                                    \
            ulonglong2 vA0_ = spA_[j];                                       \
            ulonglong2 vA1_ = spA_[j + 1];                                   \
            ulonglong2 vB0_ = spB_[j];                                       \
            ulonglong2 vB1_ = spB_[j + 1];                                   \
            FMA2(a0_, er[2 * j],     vA0_.x);                                \
            FMA2(a1_, er[2 * j + 1], vA0_.y);                                \
            FMA2(a2_, er[2 * j + 2], vA1_.x);                                \
            FMA2(a3_, er[2 * j + 3], vA1_.y);                                \
            FMA2(c0_, er[2 * j],     vB0_.x);                                \
            FMA2(c1_, er[2 * j + 1], vB0_.y);                                \
            FMA2(c2_, er[2 * j + 2], vB1_.x);                                \
            FMA2(c3_, er[2 * j + 3], vB1_.y);                                \
        }                                                                    \
        unsigned long long sA01_, sA23_, sA_, sB01_, sB23_, sB_;             \
        ADD2(sA01_, a0_, a1_); ADD2(sA23_, a2_, a3_); ADD2(sA_, sA01_, sA23_);\
        ADD2(sB01_, c0_, c1_); ADD2(sB23_, c2_, c3_); ADD2(sB_, sB01_, sB23_);\
        s_part[tag * 2 + h] = pack2(hsum2(sA_), hsum2(sB_));                 \
        PBAR();                                                              \
        ulonglong2 pq_ =                                                     \
            *reinterpret_cast<const ulonglong2*>(&s_part[tag * 2]);          \
        float nA_ = (XA) + mbA + lg2(lo2(pq_.x) + lo2(pq_.y));               \
        float nB_ = (XB2) + mbB + lg2(hi2(pq_.x) + hi2(pq_.y));              \
        betaA = (ACTA) ? nA_ : betaA;                                        \
        betaB = (ACTB) ? nB_ : betaB;                                        \
        mbA = mbAn_; mbB = mbBn_;                                            \
    }

    for (;;) {
        const bool finA = (lenA == -1) || (lenA > 0 && tA >= lenA);
        const bool finB = (lenB == -1) || (lenB > 0 && tB >= lenB);
        if (finA || finB) {
            if (lenA > 0 && tA >= lenA) EPILOGUE(bA, lenA, betaA, xbA);
            if (lenB > 0 && tB >= lenB) EPILOGUE(bB, lenB, betaB, xbB);
            __syncthreads();
            if (tid == 0) {
                int need = (finA ? 1 : 0) + (finB ? 1 : 0);
                int base = need ? atomicAdd(&g_next, need) : 0;
                s_fetch[0] = finA ? base : -2;
                s_fetch[1] = finB ? base + (finA ? 1 : 0) : -2;
            }
            __syncthreads();
            if (finA) {
                int nb = s_fetch[0];
                if (nb >= B_) lenA = 0;
                else INITSLOT(nb, bA, lenA, tA, betaA, mbA, xbA, xrA);
            }
            if (finB) {
                int nb = s_fetch[1];
                if (nb >= B_) lenB = 0;
                else INITSLOT(nb, bB, lenB, tB, betaB, mbB, xbB, xrB);
            }
            if (lenA == 0 && lenB == 0) break;
        }

        // ---- 4-step block ----
        const int tA0 = tA, tB0 = tB;
        const int clA = max(lenA - 1, 0);
        const int clB = max(lenB - 1, 0);
#pragma unroll
        for (int d = 0; d < 4; d++) {
            float cA = xrA[d], cB = xrB[d];
            int pA = min(tA0 + d + 4, clA);
            int pB = min(tB0 + d + 4, clB);
            xrA[d] = __ldg(xbA + (size_t)pA * T_ + tag) * L2E;
            xrB[d] = __ldg(xbB + (size_t)pB * T_ + tag) * L2E;
            const bool actA = (tA < lenA);
            const bool actB = (tB < lenB);
            STEP(d & 1, cA, cB, actA, actB);
            tA += actA ? 1 : 0;
            tB += actB ? 1 : 0;
        }
    }
#undef STEP
#undef INITSLOT
#undef EPILOGUE

    // ---- fused finalize: last CTA computes the mean, resets counters ----
    if (tid == 0) {
        __threadfence();
        int vd = atomicAdd(&g_done, 1);
        s_last = (vd == NCTA - 1);
    }
    __syncthreads();
    if (s_last) {
        __threadfence();
        float ts = g_diff[tid] + g_diff[tid + 256];
        ts = warp_sum(ts);
        __syncthreads();
        if (lane == 0) s_red[w] = ts;
        __syncthreads();
        if (tid == 0) {
            float total = 0.f;
#pragma unroll
            for (int k = 0; k < 8; k++) total += s_red[k];
            out[0] = total * (1.0f / B_);
            g_next = 0;
            g_done = 0;
        }
    }
#undef PBAR
}

extern "C" void kernel_launch(void* const* d_in, const int* in_sizes, int n_in,
                              void* d_out, int out_size) {
    const float* x     = (const float*)d_in[0];
    const int*   tags  = (const int*)d_in[1];
    const float* mask  = (const float*)d_in[2];
    const float* trans = (const float*)d_in[3];
    crf_kernel<<<NCTA, 256>>>(x, tags, mask, trans, (float*)d_out);
}

// round 12
// speedup vs baseline: 1.5037x; 1.5037x over previous
#include <cuda_runtime.h>

#define B_ 512
#define S_ 512
#define T_ 128
#define END_ID 1
#define L2E 1.4426950408889634f
#define LN2 0.6931471805599453f
#define PFD 4
#define NCTA 296
#define SAPAD 72   // word offset of half1 inside sa row (64 data + 8 pad)

__device__ float g_diff[B_];
__device__ int g_next = 0;
__device__ int g_done = 0;

static __device__ __forceinline__ float ex2(float x) {
    float r; asm("ex2.approx.f32 %0, %1;" : "=f"(r) : "f"(x)); return r;
}
static __device__ __forceinline__ float lg2(float x) {
    float r; asm("lg2.approx.f32 %0, %1;" : "=f"(r) : "f"(x)); return r;
}
static __device__ __forceinline__ unsigned long long pack2(float lo, float hi) {
    unsigned long long r;
    asm("mov.b64 %0, {%1, %2};" : "=l"(r) : "r"(__float_as_uint(lo)), "r"(__float_as_uint(hi)));
    return r;
}
static __device__ __forceinline__ float hsum2(unsigned long long v) {
    unsigned int a, b;
    asm("mov.b64 {%0, %1}, %2;" : "=r"(a), "=r"(b) : "l"(v));
    return __uint_as_float(a) + __uint_as_float(b);
}
#define FMA2(acc, e, a) asm("fma.rn.f32x2 %0, %1, %2, %0;" : "+l"(acc) : "l"(e), "l"(a))
#define ADD2(o, a, b)   asm("add.rn.f32x2 %0, %1, %2;" : "=l"(o) : "l"(a), "l"(b))

static __device__ __forceinline__ float warp_sum(float v) {
#pragma unroll
    for (int o = 16; o; o >>= 1) v += __shfl_xor_sync(0xffffffffu, v, o);
    return v;
}

// 256 threads, ONE chain per CTA (work-stealing), 2 CTAs/SM.
// Warp w owns tags [w*16, w*16+16); lane = 2*(tag&15) + h, h = lane&1.
// -> half-partials combine via ONE shfl_xor(1): single __syncthreads per step.
// Linear-space recurrence with exact power-of-2 renorm: no MUFU on the chain.
__global__ void __launch_bounds__(256, 2) crf_kernel(
    const float* __restrict__ x,      // [B,S,T]
    const int*   __restrict__ tags,   // [B,S]
    const float* __restrict__ mask,   // [B,S]
    const float* __restrict__ trans,  // [T,T]
    float* __restrict__ out)
{
    const int tid  = threadIdx.x;
    const int lane = tid & 31;
    const int w    = tid >> 5;          // 8 warps
    const int h    = lane & 1;          // half (adjacent lanes share a tag)
    const int tag  = w * 16 + (lane >> 1);

    __shared__ __align__(16) float sa[2][136];   // halves at [0..63] and [72..135]
    __shared__ float s_red[8];
    __shared__ int   s_b;
    __shared__ int   s_last;

    const int saw = (tag < 64) ? tag : (tag + 8);   // padded publish slot

    // ---- E regs: exp(trans[tag, h*64 .. h*64+63]) as 32 packed f32x2 ----
    unsigned long long er[32];
    {
        const float4* tr4 = reinterpret_cast<const float4*>(trans + tag * T_ + h * 64);
#pragma unroll
        for (int j = 0; j < 16; j++) {
            float4 v = __ldg(tr4 + j);
            er[2 * j]     = pack2(ex2(v.x * L2E), ex2(v.y * L2E));
            er[2 * j + 1] = pack2(ex2(v.z * L2E), ex2(v.w * L2E));
        }
    }

    // ---- persistent work-stealing over batch elements ----
    for (;;) {
        __syncthreads();
        if (tid == 0) s_b = atomicAdd(&g_next, 1);
        __syncthreads();
        const int b = s_b;
        if (b >= B_) break;

        // length = sum(mask[b,:]) (contiguous prefix); also publish a0
        float lm = mask[b * S_ + tid] + mask[b * S_ + tid + 256];
        lm = warp_sum(lm);
        if (lane == 0) s_red[w] = lm;
        if (h == 0) sa[0][saw] = (tag == 0) ? 1.f : 0.f;   // START_ID = 0
        __syncthreads();
        float lt = 0.f;
#pragma unroll
        for (int k = 0; k < 8; k++) lt += s_red[k];
        const int len = (int)(lt + 0.5f);
        const float* xb = x + (size_t)b * S_ * T_;

        // x prefetch ring: stores exp2(x * log2e) -- MUFU off the serial chain
        float xr[PFD];
#pragma unroll
        for (int d = 0; d < PFD; d++)
            xr[d] = ex2(__ldg(xb + (size_t)min(d, len - 1) * T_ + tag) * L2E);

        float na = 0.f;   // this thread's current a[tag]
        int   K  = 0;     // accumulated exact log2 renorm

#define STEP(PP, EX)                                                         \
    {                                                                        \
        __syncthreads();                                                     \
        float head_ = sa[PP][0];                                             \
        const ulonglong2* sp_ =                                              \
            reinterpret_cast<const ulonglong2*>(&sa[PP][h * SAPAD]);         \
        unsigned long long a0_ = 0ull, a1_ = 0ull, a2_ = 0ull, a3_ = 0ull;   \
        _Pragma("unroll")                                                    \
        for (int j = 0; j < 8; j++) {                                        \
            ulonglong2 v0_ = sp_[2 * j];                                     \
            ulonglong2 v1_ = sp_[2 * j + 1];                                 \
            FMA2(a0_, er[4 * j],     v0_.x);                                 \
            FMA2(a1_, er[4 * j + 1], v0_.y);                                 \
            FMA2(a2_, er[4 * j + 2], v1_.x);                                 \
            FMA2(a3_, er[4 * j + 3], v1_.y);                                 \
        }                                                                    \
        unsigned long long s01_, s23_, s_;                                   \
        ADD2(s01_, a0_, a1_); ADD2(s23_, a2_, a3_); ADD2(s_, s01_, s23_);    \
        float part_ = hsum2(s_);                                             \
        part_ += __shfl_xor_sync(0xffffffffu, part_, 1);                     \
        int kk_ = ((__float_as_int(head_) >> 23) & 255) - 127;               \
        K += kk_;                                                            \
        float sc_ = __int_as_float((127 - kk_) << 23);                       \
        na = part_ * sc_ * (EX);                                             \
        if (h == 0) sa[(PP) ^ 1][saw] = na;                                  \
    }

        int t = 0;
        const int full = (len / PFD) * PFD;
        for (; t < full; t += PFD) {
#pragma unroll
            for (int d = 0; d < PFD; d++) {
                float ex_ = xr[d];
                int pf = min(t + d + PFD, len - 1);
                xr[d] = ex2(__ldg(xb + (size_t)pf * T_ + tag) * L2E);
                STEP(d & 1, ex_);
            }
        }
#pragma unroll
        for (int d = 0; d < PFD - 1; d++) {
            if (t < len) { STEP(d & 1, xr[d]); t++; }
        }
#undef STEP

        // ---- fwd = ln2 * (lg2(sum_i a_i * exp(trans[END,i])) + K) ----
        float v = (h == 0) ? (na * ex2(__ldg(trans + END_ID * T_ + tag) * L2E))
                           : 0.f;
        v = warp_sum(v);
        __syncthreads();
        if (lane == 0) s_red[w] = v;
        __syncthreads();
        float tot = 0.f;
#pragma unroll
        for (int k = 0; k < 8; k++) tot += s_red[k];
        float fwd = (lg2(tot) + (float)K) * LN2;

        // ---- gold path score ----
        const int* tb = tags + b * S_;
        float gs = 0.f;
        for (int u = tid; u < len; u += 256) {
            int tn = tb[u + 1];
            int tc = tb[u];
            gs += xb[(size_t)u * T_ + tn] + __ldg(trans + tn * T_ + tc);
        }
        gs = warp_sum(gs);
        __syncthreads();
        if (lane == 0) s_red[w] = gs;
        __syncthreads();
        if (tid == 0) {
            float gtot = 0.f;
#pragma unroll
            for (int k = 0; k < 8; k++) gtot += s_red[k];
            gtot += __ldg(trans + END_ID * T_ + tb[len]);
            g_diff[b] = fwd - gtot;
        }
    }

    // ---- fused finalize: last CTA computes the mean, resets counters ----
    if (tid == 0) {
        __threadfence();
        int vd = atomicAdd(&g_done, 1);
        s_last = (vd == NCTA - 1);
    }
    __syncthreads();
    if (s_last) {
        __threadfence();
        float ts = g_diff[tid] + g_diff[tid + 256];
        ts = warp_sum(ts);
        __syncthreads();
        if (lane == 0) s_red[w] = ts;
        __syncthreads();
        if (tid == 0) {
            float total = 0.f;
#pragma unroll
            for (int k = 0; k < 8; k++) total += s_red[k];
            out[0] = total * (1.0f / B_);
            g_next = 0;
            g_done = 0;
        }
    }
}

extern "C" void kernel_launch(void* const* d_in, const int* in_sizes, int n_in,
                              void* d_out, int out_size) {
    const float* x     = (const float*)d_in[0];
    const int*   tags  = (const int*)d_in[1];
    const float* mask  = (const float*)d_in[2];
    const float* trans = (const float*)d_in[3];
    crf_kernel<<<NCTA, 256>>>(x, tags, mask, trans, (float*)d_out);
}